// round 9
// baseline (speedup 1.0000x reference)
#include <cuda_runtime.h>
#include <cuda_fp16.h>
#include <cstdint>

// Problem constants
#define Hh   16
#define Ss   1024
#define Dd   1024
#define HDd  64
#define Bb   8
#define BHh  (Bb*Hh)      // 128
#define Mtot (Bb*Ss)      // 8192

// fp16 scratch (device globals; no allocation allowed)
__device__ __half g_X16[(size_t)Mtot*Dd];
__device__ __half g_W16[(size_t)3*Dd*Dd];
__device__ __half g_M16[(size_t)Bb*Ss*Ss];         // fp16 mask (0/1 exact)
__device__ __half g_Q16[(size_t)BHh*Ss*HDd];       // head-major, pre-scaled by log2e/8
__device__ __half g_K16[(size_t)BHh*Ss*HDd];
__device__ __half g_V16[(size_t)BHh*Ss*HDd];

// ---------------------------------------------------------------------------
__device__ __forceinline__ uint32_t h2u(__half2 h) {
    union { __half2 h; uint32_t u; } c; c.h = h; return c.u;
}
__device__ __forceinline__ float ex2f(float x) {
    float y; asm("ex2.approx.f32 %0, %1;" : "=f"(y) : "f"(x)); return y;
}
__device__ __forceinline__ uint32_t smem_u32(const void* p) {
    uint32_t a;
    asm("{ .reg .u64 t; cvta.to.shared.u64 t, %1; cvt.u32.u64 %0, t; }" : "=r"(a) : "l"(p));
    return a;
}
#define CP_ASYNC(dst, src) \
    asm volatile("cp.async.ca.shared.global [%0], [%1], 16;" :: "r"(dst), "l"(src) : "memory")
#define CP_COMMIT() asm volatile("cp.async.commit_group;" ::: "memory")
#define CP_WAIT(n)  asm volatile("cp.async.wait_group %0;" :: "n"(n) : "memory")

__device__ __forceinline__ void ldsm_x4(uint32_t* r, uint32_t addr) {
    asm volatile("ldmatrix.sync.aligned.m8n8.x4.shared.b16 {%0,%1,%2,%3}, [%4];"
                 : "=r"(r[0]), "=r"(r[1]), "=r"(r[2]), "=r"(r[3]) : "r"(addr));
}
__device__ __forceinline__ void ldsm_x4_t(uint32_t* r, uint32_t addr) {
    asm volatile("ldmatrix.sync.aligned.m8n8.x4.trans.shared.b16 {%0,%1,%2,%3}, [%4];"
                 : "=r"(r[0]), "=r"(r[1]), "=r"(r[2]), "=r"(r[3]) : "r"(addr));
}
// fp16 m16n8k16 mma, fp32 accum in-place
__device__ __forceinline__ void mma16(float* c, const uint32_t* a, uint32_t b0, uint32_t b1) {
    asm volatile(
        "mma.sync.aligned.m16n8k16.row.col.f32.f16.f16.f32 "
        "{%0,%1,%2,%3}, {%4,%5,%6,%7}, {%8,%9}, {%0,%1,%2,%3};"
        : "+f"(c[0]), "+f"(c[1]), "+f"(c[2]), "+f"(c[3])
        : "r"(a[0]), "r"(a[1]), "r"(a[2]), "r"(a[3]), "r"(b0), "r"(b1));
}
__device__ __forceinline__ uint32_t ldsm_addr(uint32_t base, int r0, int c0b,
                                              int rowb, int lane) {
    return base + (uint32_t)(r0 + (lane & 15)) * rowb + c0b + ((lane >> 4) << 4);
}

// ---------------------------------------------------------------------------
// fp32 -> fp16 convert pre-passes
// ---------------------------------------------------------------------------
__global__ void conv_fp16(const float4* __restrict__ src, __half2* __restrict__ dst, int n4)
{
    int i = blockIdx.x * blockDim.x + threadIdx.x;
    if (i < n4) {
        float4 v = src[i];
        dst[2*i]   = __floats2half2_rn(v.x, v.y);
        dst[2*i+1] = __floats2half2_rn(v.z, v.w);
    }
}
__global__ void conv_w3(const float4* __restrict__ Wq, const float4* __restrict__ Wk,
                        const float4* __restrict__ Wv, int n4)
{
    int i = blockIdx.x * blockDim.x + threadIdx.x;
    const float4* src = (blockIdx.z == 0) ? Wq : (blockIdx.z == 1 ? Wk : Wv);
    __half2* dst = (__half2*)(g_W16 + (size_t)blockIdx.z * Dd * Dd);
    if (i < n4) {
        float4 v = src[i];
        dst[2*i]   = __floats2half2_rn(v.x, v.y);
        dst[2*i+1] = __floats2half2_rn(v.z, v.w);
    }
}

// ---------------------------------------------------------------------------
// Projection GEMM, fp16 HMMA: 512 threads, 16 warps (4x4), m32n32 per warp.
// Tile 128x128, K-step 64, 2-stage cp.async. Q pre-scaled by log2(e)/8.
// ---------------------------------------------------------------------------
#define PA_ROWB 144
#define PB_ROWB 272
#define PA_STAGE 18432
#define PB_STAGE 17408
#define PROJ_SMEM (2*PA_STAGE + 2*PB_STAGE)   // 71680

__global__ __launch_bounds__(512, 1) void proj16_kernel()
{
    extern __shared__ char sm[];
    const uint32_t sb = smem_u32(sm);
    const uint32_t Ab = sb, Bb_ = sb + 2*PA_STAGE;

    const int tid = threadIdx.x, wid = tid >> 5, lane = tid & 31;
    const int g = lane >> 2, tig = lane & 3;
    const int wm = wid & 3, wn = wid >> 2;    // 4 x 4 warp grid

    const int z  = blockIdx.z;
    const int n0 = blockIdx.x * 128;
    const int m0 = blockIdx.y * 128;
    const __half* Xp = g_X16 + (size_t)m0 * Dd;
    const __half* Wp = g_W16 + (size_t)z * Dd * Dd + n0;
    __half* Out = (z == 0) ? g_Q16 : (z == 1 ? g_K16 : g_V16);
    const float osc = (z == 0) ? 0.18033688f : 1.0f;   // log2(e)/8 folded into Q

    float C[2][4][4];
    #pragma unroll
    for (int mf = 0; mf < 2; mf++)
        #pragma unroll
        for (int nf = 0; nf < 4; nf++)
            #pragma unroll
            for (int r = 0; r < 4; r++) C[mf][nf][r] = 0.f;

    auto stage = [&](int kt, int buf) {
        const int k0 = kt * 64;
        #pragma unroll
        for (int i = 0; i < 2; i++) {           // A: 1024 16B chunks / 512 thr
            int ci = tid + 512 * i;
            int row = ci >> 3, seg = ci & 7;
            CP_ASYNC(Ab + buf * PA_STAGE + row * PA_ROWB + seg * 16,
                     Xp + (size_t)row * Dd + k0 + seg * 8);
        }
        #pragma unroll
        for (int i = 0; i < 2; i++) {           // B: 1024 16B chunks / 512 thr
            int ci = tid + 512 * i;
            int row = ci >> 4, seg = ci & 15;
            CP_ASYNC(Bb_ + buf * PB_STAGE + row * PB_ROWB + seg * 16,
                     Wp + (size_t)(k0 + row) * Dd + seg * 8);
        }
        CP_COMMIT();
    };

    stage(0, 0);
    for (int kt = 0; kt < 16; kt++) {
        if (kt < 15) { stage(kt + 1, (kt + 1) & 1); CP_WAIT(1); }
        else         { CP_WAIT(0); }
        __syncthreads();

        const uint32_t ab = Ab + (kt & 1) * PA_STAGE;
        const uint32_t bbuf = Bb_ + (kt & 1) * PB_STAGE;
        #pragma unroll
        for (int k16 = 0; k16 < 4; k16++) {
            uint32_t a[2][4];
            #pragma unroll
            for (int mf = 0; mf < 2; mf++)
                ldsm_x4(a[mf], ldsm_addr(ab, wm * 32 + mf * 16, k16 * 32, PA_ROWB, lane));
            #pragma unroll
            for (int nfp = 0; nfp < 2; nfp++) {
                uint32_t r[4];
                ldsm_x4_t(r, ldsm_addr(bbuf, k16 * 16, (wn * 32 + nfp * 16) * 2, PB_ROWB, lane));
                #pragma unroll
                for (int mf = 0; mf < 2; mf++) {
                    mma16(C[mf][2*nfp],     a[mf], r[0], r[1]);
                    mma16(C[mf][2*nfp + 1], a[mf], r[2], r[3]);
                }
            }
        }
        __syncthreads();
    }

    // epilogue: head-major fp16 scatter (warp's n32 stays within one head)
    const int h  = (n0 + wn * 32) >> 6;
    const int d0 = (wn * 32) & 63;
    #pragma unroll
    for (int mf = 0; mf < 2; mf++) {
        int m = m0 + wm * 32 + mf * 16 + g;
        int bidx = m >> 10, s = m & 1023;
        __half* base  = Out + ((size_t)(bidx * Hh + h) * Ss + s) * HDd + d0;
        __half* base2 = base + 8 * HDd;
        #pragma unroll
        for (int nf = 0; nf < 4; nf++) {
            int d = nf * 8 + 2 * tig;
            *(__half2*)(base + d)  = __floats2half2_rn(C[mf][nf][0]*osc, C[mf][nf][1]*osc);
            *(__half2*)(base2 + d) = __floats2half2_rn(C[mf][nf][2]*osc, C[mf][nf][3]*osc);
        }
    }
}

// ---------------------------------------------------------------------------
// Attention, fp16 HMMA, occupancy 2 (unchanged from R8): CTA = 128 q-rows,
// 8 warps m16 each. Full-tile S -> softmax -> PV.
// ---------------------------------------------------------------------------
#define A_ROWB 144                 // 72 halves
#define AQ_BYTES (128*A_ROWB)      // 18432
#define AKV_BYTES (64*A_ROWB)      // 9216
#define ATTN_SMEM (AQ_BYTES + 4*AKV_BYTES)   // 55296

__global__ __launch_bounds__(256, 2) void attn16_kernel(float* __restrict__ out)
{
    extern __shared__ char sm[];
    const uint32_t sb = smem_u32(sm);
    const uint32_t Qb = sb, Kb = sb + AQ_BYTES, Vb = Kb + 2*AKV_BYTES;

    const int tid = threadIdx.x, w = tid >> 5, lane = tid & 31;
    const int g = lane >> 2, tig = lane & 3;
    const int bh = blockIdx.y, b = bh >> 4, h = bh & 15;
    const int q0 = blockIdx.x * 128;
    const int i0 = w * 16;

    const __half* Qg = g_Q16 + (size_t)bh * Ss * HDd + (size_t)q0 * HDd;
    const __half* Kg = g_K16 + (size_t)bh * Ss * HDd;
    const __half* Vg = g_V16 + (size_t)bh * Ss * HDd;
    const __half* mbase = g_M16 + ((size_t)b * Ss + q0 + i0) * Ss;

    auto stageKV = [&](int t0, int buf) {
        #pragma unroll
        for (int i = 0; i < 2; i++) {          // K
            int ci = tid + 256 * i;
            int row = ci >> 3, seg = ci & 7;
            CP_ASYNC(Kb + buf * AKV_BYTES + row * A_ROWB + seg * 16,
                     Kg + (size_t)(t0 + row) * HDd + seg * 8);
        }
        #pragma unroll
        for (int i = 0; i < 2; i++) {          // V
            int ci = tid + 256 * i;
            int row = ci >> 3, seg = ci & 7;
            CP_ASYNC(Vb + buf * AKV_BYTES + row * A_ROWB + seg * 16,
                     Vg + (size_t)(t0 + row) * HDd + seg * 8);
        }
        CP_COMMIT();
    };

    // prologue: Q (1024 chunks) + KV tile 0
    #pragma unroll
    for (int i = 0; i < 4; i++) {
        int ci = tid + 256 * i;
        int row = ci >> 3, seg = ci & 7;
        CP_ASYNC(Qb + row * A_ROWB + seg * 16, Qg + (size_t)row * HDd + seg * 8);
    }
    stageKV(0, 0);
    CP_WAIT(0);
    __syncthreads();

    uint32_t qf[4][4];
    #pragma unroll
    for (int k16 = 0; k16 < 4; k16++)
        ldsm_x4(qf[k16], ldsm_addr(Qb, i0, k16 * 32, A_ROWB, lane));

    float O[8][4];
    #pragma unroll
    for (int nf = 0; nf < 8; nf++)
        #pragma unroll
        for (int r = 0; r < 4; r++) O[nf][r] = 0.f;
    float rs0 = 0.f, rs1 = 0.f;

    for (int t = 0; t < 16; t++) {
        const int t0 = t * 64, buf = t & 1;
        if (t < 15) { stageKV(t0 + 64, buf ^ 1); CP_WAIT(1); }
        else        { CP_WAIT(0); }
        __syncthreads();

        // S = Q K^T (log2 units; Q prescaled)
        float S[8][4];
        #pragma unroll
        for (int nf = 0; nf < 8; nf++)
            #pragma unroll
            for (int r = 0; r < 4; r++) S[nf][r] = 0.f;
        const uint32_t kb = Kb + buf * AKV_BYTES;
        #pragma unroll
        for (int k16 = 0; k16 < 4; k16++) {
            #pragma unroll
            for (int nfp = 0; nfp < 4; nfp++) {
                uint32_t r[4];
                ldsm_x4(r, ldsm_addr(kb, nfp * 16, k16 * 32, A_ROWB, lane));
                mma16(S[2*nfp],     qf[k16], r[0], r[2]);
                mma16(S[2*nfp + 1], qf[k16], r[1], r[3]);
            }
        }

        // P = ex2(S) * mask (fp16 mask loads), packed fp16; rowsum fp32
        uint32_t Pp[8][2];
        #pragma unroll
        for (int nf = 0; nf < 8; nf++) {
            const __half* mp = mbase + (size_t)g * Ss + t0 + nf * 8 + 2 * tig;
            float2 m01 = __half22float2(*(const __half2*)mp);
            float2 m23 = __half22float2(*(const __half2*)(mp + 8 * Ss));
            float e0 = ex2f(S[nf][0]) * m01.x;
            float e1 = ex2f(S[nf][1]) * m01.y;
            float e2 = ex2f(S[nf][2]) * m23.x;
            float e3 = ex2f(S[nf][3]) * m23.y;
            rs0 += e0 + e1;
            rs1 += e2 + e3;
            Pp[nf][0] = h2u(__floats2half2_rn(e0, e1));
            Pp[nf][1] = h2u(__floats2half2_rn(e2, e3));
        }

        // O += P V
        const uint32_t vb = Vb + buf * AKV_BYTES;
        #pragma unroll
        for (int kt = 0; kt < 4; kt++) {
            #pragma unroll
            for (int nfp = 0; nfp < 4; nfp++) {
                uint32_t r[4];
                ldsm_x4_t(r, ldsm_addr(vb, kt * 16, nfp * 32, A_ROWB, lane));
                uint32_t a[4] = { Pp[2*kt][0], Pp[2*kt][1],
                                  Pp[2*kt + 1][0], Pp[2*kt + 1][1] };
                mma16(O[2*nfp],     a, r[0], r[1]);
                mma16(O[2*nfp + 1], a, r[2], r[3]);
            }
        }
        __syncthreads();
    }

    // normalize + store
    rs0 += __shfl_xor_sync(0xffffffffu, rs0, 1);
    rs0 += __shfl_xor_sync(0xffffffffu, rs0, 2);
    rs1 += __shfl_xor_sync(0xffffffffu, rs1, 1);
    rs1 += __shfl_xor_sync(0xffffffffu, rs1, 2);
    const float inv0 = 1.0f / (rs0 + 1e-8f);
    const float inv1 = 1.0f / (rs1 + 1e-8f);
    float* o0 = out + ((size_t)b * Ss + q0 + i0 + g) * Dd + h * HDd;
    float* o1 = o0 + 8 * Dd;
    #pragma unroll
    for (int nf = 0; nf < 8; nf++) {
        int d = nf * 8 + 2 * tig;
        *(float2*)(o0 + d) = make_float2(O[nf][0] * inv0, O[nf][1] * inv0);
        *(float2*)(o1 + d) = make_float2(O[nf][2] * inv1, O[nf][3] * inv1);
    }
}

// ---------------------------------------------------------------------------
extern "C" void kernel_launch(void* const* d_in, const int* in_sizes, int n_in,
                              void* d_out, int out_size)
{
    const float* x    = (const float*)d_in[0];
    const float* mask = (const float*)d_in[1];
    const float* Wq   = (const float*)d_in[2];
    const float* Wk   = (const float*)d_in[3];
    const float* Wv   = (const float*)d_in[4];
    float* out = (float*)d_out;

    __half* gX; cudaGetSymbolAddress((void**)&gX, g_X16);
    __half* gM; cudaGetSymbolAddress((void**)&gM, g_M16);

    // 1) fp32 -> fp16 pre-pass (x, weights, mask)
    const int n4x = Mtot * Dd / 4;
    const int n4w = Dd * Dd / 4;
    const int n4m = Bb * Ss * Ss / 4;
    conv_fp16<<<(n4x + 255) / 256, 256>>>((const float4*)x, (__half2*)gX, n4x);
    {
        dim3 wgrid((n4w + 255) / 256, 1, 3);
        conv_w3<<<wgrid, 256>>>((const float4*)Wq, (const float4*)Wk,
                                (const float4*)Wv, n4w);
    }
    conv_fp16<<<(n4m + 255) / 256, 256>>>((const float4*)mask, (__half2*)gM, n4m);

    // 2) projections (fp16 HMMA, 512 thr / 16 warps)
    cudaFuncSetAttribute(proj16_kernel, cudaFuncAttributeMaxDynamicSharedMemorySize,
                         PROJ_SMEM);
    dim3 pgrid(Dd / 128, Mtot / 128, 3);
    proj16_kernel<<<pgrid, 512, PROJ_SMEM>>>();

    // 3) attention (fp16 HMMA, occ 2)
    cudaFuncSetAttribute(attn16_kernel, cudaFuncAttributeMaxDynamicSharedMemorySize,
                         ATTN_SMEM);
    dim3 agrid(Ss / 128, BHh);              // (8, 128)
    attn16_kernel<<<agrid, 256, ATTN_SMEM>>>(out);
}

// round 11
// speedup vs baseline: 1.0314x; 1.0314x over previous
#include <cuda_runtime.h>
#include <cuda_fp16.h>
#include <cstdint>

// Problem constants
#define Hh   16
#define Ss   1024
#define Dd   1024
#define HDd  64
#define Bb   8
#define BHh  (Bb*Hh)      // 128
#define Mtot (Bb*Ss)      // 8192

// fp16 scratch (device globals; no allocation allowed)
__device__ __half g_X16[(size_t)Mtot*Dd];
__device__ __half g_W16[(size_t)3*Dd*Dd];
__device__ __half g_M16[(size_t)Bb*Ss*Ss];         // fp16 mask (0/1 exact)
__device__ __half g_Q16[(size_t)BHh*Ss*HDd];       // head-major, pre-scaled by log2e/8
__device__ __half g_K16[(size_t)BHh*Ss*HDd];
__device__ __half g_V16[(size_t)BHh*Ss*HDd];

// ---------------------------------------------------------------------------
__device__ __forceinline__ uint32_t h2u(__half2 h) {
    union { __half2 h; uint32_t u; } c; c.h = h; return c.u;
}
__device__ __forceinline__ float ex2f(float x) {
    float y; asm("ex2.approx.f32 %0, %1;" : "=f"(y) : "f"(x)); return y;
}
__device__ __forceinline__ uint32_t smem_u32(const void* p) {
    uint32_t a;
    asm("{ .reg .u64 t; cvta.to.shared.u64 t, %1; cvt.u32.u64 %0, t; }" : "=r"(a) : "l"(p));
    return a;
}
#define CP_ASYNC(dst, src) \
    asm volatile("cp.async.ca.shared.global [%0], [%1], 16;" :: "r"(dst), "l"(src) : "memory")
#define CP_COMMIT() asm volatile("cp.async.commit_group;" ::: "memory")
#define CP_WAIT(n)  asm volatile("cp.async.wait_group %0;" :: "n"(n) : "memory")

__device__ __forceinline__ void ldsm_x4(uint32_t* r, uint32_t addr) {
    asm volatile("ldmatrix.sync.aligned.m8n8.x4.shared.b16 {%0,%1,%2,%3}, [%4];"
                 : "=r"(r[0]), "=r"(r[1]), "=r"(r[2]), "=r"(r[3]) : "r"(addr));
}
__device__ __forceinline__ void ldsm_x4_t(uint32_t* r, uint32_t addr) {
    asm volatile("ldmatrix.sync.aligned.m8n8.x4.trans.shared.b16 {%0,%1,%2,%3}, [%4];"
                 : "=r"(r[0]), "=r"(r[1]), "=r"(r[2]), "=r"(r[3]) : "r"(addr));
}
// fp16 m16n8k16 mma, fp32 accum in-place
__device__ __forceinline__ void mma16(float* c, const uint32_t* a, uint32_t b0, uint32_t b1) {
    asm volatile(
        "mma.sync.aligned.m16n8k16.row.col.f32.f16.f16.f32 "
        "{%0,%1,%2,%3}, {%4,%5,%6,%7}, {%8,%9}, {%0,%1,%2,%3};"
        : "+f"(c[0]), "+f"(c[1]), "+f"(c[2]), "+f"(c[3])
        : "r"(a[0]), "r"(a[1]), "r"(a[2]), "r"(a[3]), "r"(b0), "r"(b1));
}
__device__ __forceinline__ uint32_t ldsm_addr(uint32_t base, int r0, int c0b,
                                              int rowb, int lane) {
    return base + (uint32_t)(r0 + (lane & 15)) * rowb + c0b + ((lane >> 4) << 4);
}

// ---------------------------------------------------------------------------
// fp32 -> fp16 convert pre-passes
// ---------------------------------------------------------------------------
__global__ void conv_fp16(const float4* __restrict__ src, __half2* __restrict__ dst, int n4)
{
    int i = blockIdx.x * blockDim.x + threadIdx.x;
    if (i < n4) {
        float4 v = src[i];
        dst[2*i]   = __floats2half2_rn(v.x, v.y);
        dst[2*i+1] = __floats2half2_rn(v.z, v.w);
    }
}
__global__ void conv_w3(const float4* __restrict__ Wq, const float4* __restrict__ Wk,
                        const float4* __restrict__ Wv, int n4)
{
    int i = blockIdx.x * blockDim.x + threadIdx.x;
    const float4* src = (blockIdx.z == 0) ? Wq : (blockIdx.z == 1 ? Wk : Wv);
    __half2* dst = (__half2*)(g_W16 + (size_t)blockIdx.z * Dd * Dd);
    if (i < n4) {
        float4 v = src[i];
        dst[2*i]   = __floats2half2_rn(v.x, v.y);
        dst[2*i+1] = __floats2half2_rn(v.z, v.w);
    }
}

// ---------------------------------------------------------------------------
// Projection GEMM, fp16 HMMA: 256 thr, 8 warps, m32n64/warp, tile 128x128,
// K-step 64, 3-stage cp.async pipeline + register-level ldsm prefetch.
// Tail fix: last iteration uses CP_WAIT(0) (its group is the newest commit).
// Q output pre-scaled by log2(e)/8.
// ---------------------------------------------------------------------------
#define PA_ROWB 144
#define PB_ROWB 272
#define PA_STAGE 18432
#define PB_STAGE 17408
#define NSTG 3
#define PROJ_SMEM (NSTG*(PA_STAGE + PB_STAGE))   // 107520

__global__ __launch_bounds__(256, 1) void proj16_kernel()
{
    extern __shared__ char sm[];
    const uint32_t sb = smem_u32(sm);
    const uint32_t Ab = sb, Bb_ = sb + NSTG*PA_STAGE;

    const int tid = threadIdx.x, wid = tid >> 5, lane = tid & 31;
    const int g = lane >> 2, tig = lane & 3;
    const int wm = wid & 3, wn = wid >> 2;

    const int z  = blockIdx.z;
    const int n0 = blockIdx.x * 128;
    const int m0 = blockIdx.y * 128;
    const __half* Xp = g_X16 + (size_t)m0 * Dd;
    const __half* Wp = g_W16 + (size_t)z * Dd * Dd + n0;
    __half* Out = (z == 0) ? g_Q16 : (z == 1 ? g_K16 : g_V16);
    const float osc = (z == 0) ? 0.18033688f : 1.0f;   // log2(e)/8 folded into Q

    float C[2][8][4];
    #pragma unroll
    for (int mf = 0; mf < 2; mf++)
        #pragma unroll
        for (int nf = 0; nf < 8; nf++)
            #pragma unroll
            for (int r = 0; r < 4; r++) C[mf][nf][r] = 0.f;

    auto stage = [&](int kt, int buf) {
        const int k0 = kt * 64;
        #pragma unroll
        for (int i = 0; i < 4; i++) {
            int ci = tid + 256 * i;
            int row = ci >> 3, seg = ci & 7;
            CP_ASYNC(Ab + buf * PA_STAGE + row * PA_ROWB + seg * 16,
                     Xp + (size_t)row * Dd + k0 + seg * 8);
        }
        #pragma unroll
        for (int i = 0; i < 4; i++) {
            int ci = tid + 256 * i;
            int row = ci >> 4, seg = ci & 15;
            CP_ASYNC(Bb_ + buf * PB_STAGE + row * PB_ROWB + seg * 16,
                     Wp + (size_t)(k0 + row) * Dd + seg * 8);
        }
        CP_COMMIT();
    };

    stage(0, 0);
    stage(1, 1);
    for (int kt = 0; kt < 16; kt++) {
        // Tail-correct wait: group kt is complete when <=1 newer groups pending,
        // except at kt==15 where group 15 IS the newest -> must wait for all.
        if (kt == 15) { CP_WAIT(0); }
        else          { CP_WAIT(1); }
        __syncthreads();

        const int buf = kt % NSTG;
        const uint32_t ab = Ab + buf * PA_STAGE;
        const uint32_t bbuf = Bb_ + buf * PB_STAGE;

        // register-pipelined fragment loads: prefetch k16+1 while k16's MMAs issue
        uint32_t a[2][4], an[2][4], r[4], rn[4];
        ldsm_x4(a[0], ldsm_addr(ab, wm * 32,      0, PA_ROWB, lane));
        ldsm_x4(a[1], ldsm_addr(ab, wm * 32 + 16, 0, PA_ROWB, lane));
        ldsm_x4_t(r, ldsm_addr(bbuf, 0, (wn * 64) * 2, PB_ROWB, lane));

        #pragma unroll
        for (int k16 = 0; k16 < 4; k16++) {
            #pragma unroll
            for (int nfp = 0; nfp < 4; nfp++) {
                if (nfp < 3) {
                    ldsm_x4_t(rn, ldsm_addr(bbuf, k16 * 16,
                                            (wn * 64 + (nfp + 1) * 16) * 2, PB_ROWB, lane));
                } else if (k16 < 3) {
                    ldsm_x4_t(rn, ldsm_addr(bbuf, (k16 + 1) * 16,
                                            (wn * 64) * 2, PB_ROWB, lane));
                    ldsm_x4(an[0], ldsm_addr(ab, wm * 32,      (k16 + 1) * 32, PA_ROWB, lane));
                    ldsm_x4(an[1], ldsm_addr(ab, wm * 32 + 16, (k16 + 1) * 32, PA_ROWB, lane));
                }
                mma16(C[0][2*nfp],     a[0], r[0], r[1]);
                mma16(C[0][2*nfp + 1], a[0], r[2], r[3]);
                mma16(C[1][2*nfp],     a[1], r[0], r[1]);
                mma16(C[1][2*nfp + 1], a[1], r[2], r[3]);
                #pragma unroll
                for (int q = 0; q < 4; q++) r[q] = rn[q];
            }
            #pragma unroll
            for (int q = 0; q < 4; q++) { a[0][q] = an[0][q]; a[1][q] = an[1][q]; }
        }

        __syncthreads();
        if (kt + 2 < 16) stage(kt + 2, (kt + 2) % NSTG);
    }

    // epilogue: head-major fp16 scatter
    const int h = (n0 >> 6) + wn;
    #pragma unroll
    for (int mf = 0; mf < 2; mf++) {
        int m = m0 + wm * 32 + mf * 16 + g;
        int bidx = m >> 10, s = m & 1023;
        __half* base  = Out + ((size_t)(bidx * Hh + h) * Ss + s) * HDd;
        __half* base2 = base + 8 * HDd;
        #pragma unroll
        for (int nf = 0; nf < 8; nf++) {
            int d = nf * 8 + 2 * tig;
            *(__half2*)(base + d)  = __floats2half2_rn(C[mf][nf][0]*osc, C[mf][nf][1]*osc);
            *(__half2*)(base2 + d) = __floats2half2_rn(C[mf][nf][2]*osc, C[mf][nf][3]*osc);
        }
    }
}

// ---------------------------------------------------------------------------
// Attention, fp16 HMMA, occupancy 2 (unchanged from R8): CTA = 128 q-rows,
// 8 warps m16 each. Full-tile S -> softmax -> PV.
// ---------------------------------------------------------------------------
#define A_ROWB 144                 // 72 halves
#define AQ_BYTES (128*A_ROWB)      // 18432
#define AKV_BYTES (64*A_ROWB)      // 9216
#define ATTN_SMEM (AQ_BYTES + 4*AKV_BYTES)   // 55296

__global__ __launch_bounds__(256, 2) void attn16_kernel(float* __restrict__ out)
{
    extern __shared__ char sm[];
    const uint32_t sb = smem_u32(sm);
    const uint32_t Qb = sb, Kb = sb + AQ_BYTES, Vb = Kb + 2*AKV_BYTES;

    const int tid = threadIdx.x, w = tid >> 5, lane = tid & 31;
    const int g = lane >> 2, tig = lane & 3;
    const int bh = blockIdx.y, b = bh >> 4, h = bh & 15;
    const int q0 = blockIdx.x * 128;
    const int i0 = w * 16;

    const __half* Qg = g_Q16 + (size_t)bh * Ss * HDd + (size_t)q0 * HDd;
    const __half* Kg = g_K16 + (size_t)bh * Ss * HDd;
    const __half* Vg = g_V16 + (size_t)bh * Ss * HDd;
    const __half* mbase = g_M16 + ((size_t)b * Ss + q0 + i0) * Ss;

    auto stageKV = [&](int t0, int buf) {
        #pragma unroll
        for (int i = 0; i < 2; i++) {          // K
            int ci = tid + 256 * i;
            int row = ci >> 3, seg = ci & 7;
            CP_ASYNC(Kb + buf * AKV_BYTES + row * A_ROWB + seg * 16,
                     Kg + (size_t)(t0 + row) * HDd + seg * 8);
        }
        #pragma unroll
        for (int i = 0; i < 2; i++) {          // V
            int ci = tid + 256 * i;
            int row = ci >> 3, seg = ci & 7;
            CP_ASYNC(Vb + buf * AKV_BYTES + row * A_ROWB + seg * 16,
                     Vg + (size_t)(t0 + row) * HDd + seg * 8);
        }
        CP_COMMIT();
    };

    // prologue: Q (1024 chunks) + KV tile 0
    #pragma unroll
    for (int i = 0; i < 4; i++) {
        int ci = tid + 256 * i;
        int row = ci >> 3, seg = ci & 7;
        CP_ASYNC(Qb + row * A_ROWB + seg * 16, Qg + (size_t)row * HDd + seg * 8);
    }
    stageKV(0, 0);
    CP_WAIT(0);
    __syncthreads();

    uint32_t qf[4][4];
    #pragma unroll
    for (int k16 = 0; k16 < 4; k16++)
        ldsm_x4(qf[k16], ldsm_addr(Qb, i0, k16 * 32, A_ROWB, lane));

    float O[8][4];
    #pragma unroll
    for (int nf = 0; nf < 8; nf++)
        #pragma unroll
        for (int r = 0; r < 4; r++) O[nf][r] = 0.f;
    float rs0 = 0.f, rs1 = 0.f;

    for (int t = 0; t < 16; t++) {
        const int t0 = t * 64, buf = t & 1;
        if (t < 15) { stageKV(t0 + 64, buf ^ 1); CP_WAIT(1); }
        else        { CP_WAIT(0); }
        __syncthreads();

        // S = Q K^T (log2 units; Q prescaled)
        float S[8][4];
        #pragma unroll
        for (int nf = 0; nf < 8; nf++)
            #pragma unroll
            for (int r = 0; r < 4; r++) S[nf][r] = 0.f;
        const uint32_t kb = Kb + buf * AKV_BYTES;
        #pragma unroll
        for (int k16 = 0; k16 < 4; k16++) {
            #pragma unroll
            for (int nfp = 0; nfp < 4; nfp++) {
                uint32_t r[4];
                ldsm_x4(r, ldsm_addr(kb, nfp * 16, k16 * 32, A_ROWB, lane));
                mma16(S[2*nfp],     qf[k16], r[0], r[2]);
                mma16(S[2*nfp + 1], qf[k16], r[1], r[3]);
            }
        }

        // P = ex2(S) * mask (fp16 mask loads), packed fp16; rowsum fp32
        uint32_t Pp[8][2];
        #pragma unroll
        for (int nf = 0; nf < 8; nf++) {
            const __half* mp = mbase + (size_t)g * Ss + t0 + nf * 8 + 2 * tig;
            float2 m01 = __half22float2(*(const __half2*)mp);
            float2 m23 = __half22float2(*(const __half2*)(mp + 8 * Ss));
            float e0 = ex2f(S[nf][0]) * m01.x;
            float e1 = ex2f(S[nf][1]) * m01.y;
            float e2 = ex2f(S[nf][2]) * m23.x;
            float e3 = ex2f(S[nf][3]) * m23.y;
            rs0 += e0 + e1;
            rs1 += e2 + e3;
            Pp[nf][0] = h2u(__floats2half2_rn(e0, e1));
            Pp[nf][1] = h2u(__floats2half2_rn(e2, e3));
        }

        // O += P V
        const uint32_t vb = Vb + buf * AKV_BYTES;
        #pragma unroll
        for (int kt = 0; kt < 4; kt++) {
            #pragma unroll
            for (int nfp = 0; nfp < 4; nfp++) {
                uint32_t r[4];
                ldsm_x4_t(r, ldsm_addr(vb, kt * 16, nfp * 32, A_ROWB, lane));
                uint32_t a[4] = { Pp[2*kt][0], Pp[2*kt][1],
                                  Pp[2*kt + 1][0], Pp[2*kt + 1][1] };
                mma16(O[2*nfp],     a, r[0], r[1]);
                mma16(O[2*nfp + 1], a, r[2], r[3]);
            }
        }
        __syncthreads();
    }

    // normalize + store
    rs0 += __shfl_xor_sync(0xffffffffu, rs0, 1);
    rs0 += __shfl_xor_sync(0xffffffffu, rs0, 2);
    rs1 += __shfl_xor_sync(0xffffffffu, rs1, 1);
    rs1 += __shfl_xor_sync(0xffffffffu, rs1, 2);
    const float inv0 = 1.0f / (rs0 + 1e-8f);
    const float inv1 = 1.0f / (rs1 + 1e-8f);
    float* o0 = out + ((size_t)b * Ss + q0 + i0 + g) * Dd + h * HDd;
    float* o1 = o0 + 8 * Dd;
    #pragma unroll
    for (int nf = 0; nf < 8; nf++) {
        int d = nf * 8 + 2 * tig;
        *(float2*)(o0 + d) = make_float2(O[nf][0] * inv0, O[nf][1] * inv0);
        *(float2*)(o1 + d) = make_float2(O[nf][2] * inv1, O[nf][3] * inv1);
    }
}

// ---------------------------------------------------------------------------
extern "C" void kernel_launch(void* const* d_in, const int* in_sizes, int n_in,
                              void* d_out, int out_size)
{
    const float* x    = (const float*)d_in[0];
    const float* mask = (const float*)d_in[1];
    const float* Wq   = (const float*)d_in[2];
    const float* Wk   = (const float*)d_in[3];
    const float* Wv   = (const float*)d_in[4];
    float* out = (float*)d_out;

    __half* gX; cudaGetSymbolAddress((void**)&gX, g_X16);
    __half* gM; cudaGetSymbolAddress((void**)&gM, g_M16);

    // 1) fp32 -> fp16 pre-pass (x, weights, mask)
    const int n4x = Mtot * Dd / 4;
    const int n4w = Dd * Dd / 4;
    const int n4m = Bb * Ss * Ss / 4;
    conv_fp16<<<(n4x + 255) / 256, 256>>>((const float4*)x, (__half2*)gX, n4x);
    {
        dim3 wgrid((n4w + 255) / 256, 1, 3);
        conv_w3<<<wgrid, 256>>>((const float4*)Wq, (const float4*)Wk,
                                (const float4*)Wv, n4w);
    }
    conv_fp16<<<(n4m + 255) / 256, 256>>>((const float4*)mask, (__half2*)gM, n4m);

    // 2) projections (fp16 HMMA, 3-stage pipeline + ldsm prefetch, tail-fixed)
    cudaFuncSetAttribute(proj16_kernel, cudaFuncAttributeMaxDynamicSharedMemorySize,
                         PROJ_SMEM);
    dim3 pgrid(Dd / 128, Mtot / 128, 3);
    proj16_kernel<<<pgrid, 256, PROJ_SMEM>>>();

    // 3) attention (fp16 HMMA, occ 2)
    cudaFuncSetAttribute(attn16_kernel, cudaFuncAttributeMaxDynamicSharedMemorySize,
                         ATTN_SMEM);
    dim3 agrid(Ss / 128, BHh);              // (8, 128)
    attn16_kernel<<<agrid, 256, ATTN_SMEM>>>(out);
}

// round 12
// speedup vs baseline: 1.1090x; 1.0752x over previous
#include <cuda_runtime.h>
#include <cuda_fp16.h>
#include <cstdint>

// Problem constants
#define Hh   16
#define Ss   1024
#define Dd   1024
#define HDd  64
#define Bb   8
#define BHh  (Bb*Hh)      // 128
#define Mtot (Bb*Ss)      // 8192

// fp16 scratch (device globals; no allocation allowed)
__device__ __half g_X16[(size_t)Mtot*Dd];
__device__ __half g_W16[(size_t)3*Dd*Dd];
__device__ __half g_M16[(size_t)Bb*Ss*Ss];         // fp16 mask (0/1 exact)
__device__ __half g_Q16[(size_t)BHh*Ss*HDd];       // head-major, pre-scaled by log2e/8
__device__ __half g_K16[(size_t)BHh*Ss*HDd];
__device__ __half g_V16[(size_t)BHh*Ss*HDd];

// ---------------------------------------------------------------------------
__device__ __forceinline__ uint32_t h2u(__half2 h) {
    union { __half2 h; uint32_t u; } c; c.h = h; return c.u;
}
__device__ __forceinline__ float ex2f(float x) {
    float y; asm("ex2.approx.f32 %0, %1;" : "=f"(y) : "f"(x)); return y;
}
__device__ __forceinline__ uint32_t smem_u32(const void* p) {
    uint32_t a;
    asm("{ .reg .u64 t; cvta.to.shared.u64 t, %1; cvt.u32.u64 %0, t; }" : "=r"(a) : "l"(p));
    return a;
}
#define CP_ASYNC(dst, src) \
    asm volatile("cp.async.ca.shared.global [%0], [%1], 16;" :: "r"(dst), "l"(src) : "memory")
#define CP_COMMIT() asm volatile("cp.async.commit_group;" ::: "memory")
#define CP_WAIT(n)  asm volatile("cp.async.wait_group %0;" :: "n"(n) : "memory")

__device__ __forceinline__ void ldsm_x4(uint32_t* r, uint32_t addr) {
    asm volatile("ldmatrix.sync.aligned.m8n8.x4.shared.b16 {%0,%1,%2,%3}, [%4];"
                 : "=r"(r[0]), "=r"(r[1]), "=r"(r[2]), "=r"(r[3]) : "r"(addr));
}
__device__ __forceinline__ void ldsm_x4_t(uint32_t* r, uint32_t addr) {
    asm volatile("ldmatrix.sync.aligned.m8n8.x4.trans.shared.b16 {%0,%1,%2,%3}, [%4];"
                 : "=r"(r[0]), "=r"(r[1]), "=r"(r[2]), "=r"(r[3]) : "r"(addr));
}
// fp16 m16n8k16 mma, fp32 accum in-place
__device__ __forceinline__ void mma16(float* c, const uint32_t* a, uint32_t b0, uint32_t b1) {
    asm volatile(
        "mma.sync.aligned.m16n8k16.row.col.f32.f16.f16.f32 "
        "{%0,%1,%2,%3}, {%4,%5,%6,%7}, {%8,%9}, {%0,%1,%2,%3};"
        : "+f"(c[0]), "+f"(c[1]), "+f"(c[2]), "+f"(c[3])
        : "r"(a[0]), "r"(a[1]), "r"(a[2]), "r"(a[3]), "r"(b0), "r"(b1));
}
__device__ __forceinline__ uint32_t ldsm_addr(uint32_t base, int r0, int c0b,
                                              int rowb, int lane) {
    return base + (uint32_t)(r0 + (lane & 15)) * rowb + c0b + ((lane >> 4) << 4);
}

// ---------------------------------------------------------------------------
// fp32 -> fp16 convert pre-passes
// ---------------------------------------------------------------------------
__global__ void conv_fp16(const float4* __restrict__ src, __half2* __restrict__ dst, int n4)
{
    int i = blockIdx.x * blockDim.x + threadIdx.x;
    if (i < n4) {
        float4 v = src[i];
        dst[2*i]   = __floats2half2_rn(v.x, v.y);
        dst[2*i+1] = __floats2half2_rn(v.z, v.w);
    }
}
__global__ void conv_w3(const float4* __restrict__ Wq, const float4* __restrict__ Wk,
                        const float4* __restrict__ Wv, int n4)
{
    int i = blockIdx.x * blockDim.x + threadIdx.x;
    const float4* src = (blockIdx.z == 0) ? Wq : (blockIdx.z == 1 ? Wk : Wv);
    __half2* dst = (__half2*)(g_W16 + (size_t)blockIdx.z * Dd * Dd);
    if (i < n4) {
        float4 v = src[i];
        dst[2*i]   = __floats2half2_rn(v.x, v.y);
        dst[2*i+1] = __floats2half2_rn(v.z, v.w);
    }
}

// ---------------------------------------------------------------------------
// Projection GEMM, fp16 HMMA: 256 thr, 8 warps, m32n64/warp, tile 128x128,
// K-step 64, 3-stage cp.async pipeline, SINGLE barrier per K-step.
// Order per iter: wait -> sync -> stage(kt+2) -> compute. The leading sync
// guarantees all warps finished iter kt-1 before stage overwrites its buffer.
// Q output pre-scaled by log2(e)/8.
// ---------------------------------------------------------------------------
#define PA_ROWB 144
#define PB_ROWB 272
#define PA_STAGE 18432
#define PB_STAGE 17408
#define NSTG 3
#define PROJ_SMEM (NSTG*(PA_STAGE + PB_STAGE))   // 107520

__global__ __launch_bounds__(256, 1) void proj16_kernel()
{
    extern __shared__ char sm[];
    const uint32_t sb = smem_u32(sm);
    const uint32_t Ab = sb, Bb_ = sb + NSTG*PA_STAGE;

    const int tid = threadIdx.x, wid = tid >> 5, lane = tid & 31;
    const int g = lane >> 2, tig = lane & 3;
    const int wm = wid & 3, wn = wid >> 2;

    const int z  = blockIdx.z;
    const int n0 = blockIdx.x * 128;
    const int m0 = blockIdx.y * 128;
    const __half* Xp = g_X16 + (size_t)m0 * Dd;
    const __half* Wp = g_W16 + (size_t)z * Dd * Dd + n0;
    __half* Out = (z == 0) ? g_Q16 : (z == 1 ? g_K16 : g_V16);
    const float osc = (z == 0) ? 0.18033688f : 1.0f;   // log2(e)/8 folded into Q

    float C[2][8][4];
    #pragma unroll
    for (int mf = 0; mf < 2; mf++)
        #pragma unroll
        for (int nf = 0; nf < 8; nf++)
            #pragma unroll
            for (int r = 0; r < 4; r++) C[mf][nf][r] = 0.f;

    auto stage = [&](int kt, int buf) {
        const int k0 = kt * 64;
        #pragma unroll
        for (int i = 0; i < 4; i++) {
            int ci = tid + 256 * i;
            int row = ci >> 3, seg = ci & 7;
            CP_ASYNC(Ab + buf * PA_STAGE + row * PA_ROWB + seg * 16,
                     Xp + (size_t)row * Dd + k0 + seg * 8);
        }
        #pragma unroll
        for (int i = 0; i < 4; i++) {
            int ci = tid + 256 * i;
            int row = ci >> 4, seg = ci & 15;
            CP_ASYNC(Bb_ + buf * PB_STAGE + row * PB_ROWB + seg * 16,
                     Wp + (size_t)(k0 + row) * Dd + seg * 8);
        }
        CP_COMMIT();
    };

    stage(0, 0);
    stage(1, 1);
    for (int kt = 0; kt < 16; kt++) {
        // group ledger: committed 0..kt+1 here; WAIT(1) => group kt complete.
        // kt==15: group 15 is the newest commit -> must wait for all.
        if (kt == 15) { CP_WAIT(0); }
        else          { CP_WAIT(1); }
        __syncthreads();   // all warps done with iter kt-1 (buf (kt-1)%3)
        if (kt + 2 < 16) stage(kt + 2, (kt + 2) % NSTG);   // writes buf (kt-1)%3

        const int buf = kt % NSTG;
        const uint32_t ab = Ab + buf * PA_STAGE;
        const uint32_t bbuf = Bb_ + buf * PB_STAGE;

        // register-pipelined fragment loads
        uint32_t a[2][4], an[2][4], r[4], rn[4];
        ldsm_x4(a[0], ldsm_addr(ab, wm * 32,      0, PA_ROWB, lane));
        ldsm_x4(a[1], ldsm_addr(ab, wm * 32 + 16, 0, PA_ROWB, lane));
        ldsm_x4_t(r, ldsm_addr(bbuf, 0, (wn * 64) * 2, PB_ROWB, lane));

        #pragma unroll
        for (int k16 = 0; k16 < 4; k16++) {
            #pragma unroll
            for (int nfp = 0; nfp < 4; nfp++) {
                if (nfp < 3) {
                    ldsm_x4_t(rn, ldsm_addr(bbuf, k16 * 16,
                                            (wn * 64 + (nfp + 1) * 16) * 2, PB_ROWB, lane));
                } else if (k16 < 3) {
                    ldsm_x4_t(rn, ldsm_addr(bbuf, (k16 + 1) * 16,
                                            (wn * 64) * 2, PB_ROWB, lane));
                    ldsm_x4(an[0], ldsm_addr(ab, wm * 32,      (k16 + 1) * 32, PA_ROWB, lane));
                    ldsm_x4(an[1], ldsm_addr(ab, wm * 32 + 16, (k16 + 1) * 32, PA_ROWB, lane));
                }
                mma16(C[0][2*nfp],     a[0], r[0], r[1]);
                mma16(C[0][2*nfp + 1], a[0], r[2], r[3]);
                mma16(C[1][2*nfp],     a[1], r[0], r[1]);
                mma16(C[1][2*nfp + 1], a[1], r[2], r[3]);
                #pragma unroll
                for (int q = 0; q < 4; q++) r[q] = rn[q];
            }
            #pragma unroll
            for (int q = 0; q < 4; q++) { a[0][q] = an[0][q]; a[1][q] = an[1][q]; }
        }
    }

    // epilogue: head-major fp16 scatter
    const int h = (n0 >> 6) + wn;
    #pragma unroll
    for (int mf = 0; mf < 2; mf++) {
        int m = m0 + wm * 32 + mf * 16 + g;
        int bidx = m >> 10, s = m & 1023;
        __half* base  = Out + ((size_t)(bidx * Hh + h) * Ss + s) * HDd;
        __half* base2 = base + 8 * HDd;
        #pragma unroll
        for (int nf = 0; nf < 8; nf++) {
            int d = nf * 8 + 2 * tig;
            *(__half2*)(base + d)  = __floats2half2_rn(C[mf][nf][0]*osc, C[mf][nf][1]*osc);
            *(__half2*)(base2 + d) = __floats2half2_rn(C[mf][nf][2]*osc, C[mf][nf][3]*osc);
        }
    }
}

// ---------------------------------------------------------------------------
// Attention, fp16 HMMA, occupancy 2: CTA = 128 q-rows, 8 warps m16 each.
// KV staged in 128-row double-buffered stages (two 64-row sub-tiles per stage):
// barriers per block 32 -> 16, wait points 16 -> 8.
// ---------------------------------------------------------------------------
#define A_ROWB 144                  // 72 halves
#define AQ_BYTES (128*A_ROWB)       // 18432
#define AKV_BYTES (128*A_ROWB)      // 18432 per 128-row stage
#define ATTN_SMEM (AQ_BYTES + 4*AKV_BYTES)   // 92160 (K x2, V x2)

__global__ __launch_bounds__(256, 2) void attn16_kernel(float* __restrict__ out)
{
    extern __shared__ char sm[];
    const uint32_t sb = smem_u32(sm);
    const uint32_t Qb = sb, Kb = sb + AQ_BYTES, Vb = Kb + 2*AKV_BYTES;

    const int tid = threadIdx.x, w = tid >> 5, lane = tid & 31;
    const int g = lane >> 2, tig = lane & 3;
    const int bh = blockIdx.y, b = bh >> 4, h = bh & 15;
    const int q0 = blockIdx.x * 128;
    const int i0 = w * 16;

    const __half* Qg = g_Q16 + (size_t)bh * Ss * HDd + (size_t)q0 * HDd;
    const __half* Kg = g_K16 + (size_t)bh * Ss * HDd;
    const __half* Vg = g_V16 + (size_t)bh * Ss * HDd;
    const __half* mbase = g_M16 + ((size_t)b * Ss + q0 + i0) * Ss;

    auto stageKV = [&](int t0, int buf) {
        #pragma unroll
        for (int i = 0; i < 4; i++) {          // K: 1024 chunks / 256 thr
            int ci = tid + 256 * i;
            int row = ci >> 3, seg = ci & 7;
            CP_ASYNC(Kb + buf * AKV_BYTES + row * A_ROWB + seg * 16,
                     Kg + (size_t)(t0 + row) * HDd + seg * 8);
        }
        #pragma unroll
        for (int i = 0; i < 4; i++) {          // V
            int ci = tid + 256 * i;
            int row = ci >> 3, seg = ci & 7;
            CP_ASYNC(Vb + buf * AKV_BYTES + row * A_ROWB + seg * 16,
                     Vg + (size_t)(t0 + row) * HDd + seg * 8);
        }
        CP_COMMIT();
    };

    // prologue: Q (1024 chunks) + KV stage 0 -> one group
    #pragma unroll
    for (int i = 0; i < 4; i++) {
        int ci = tid + 256 * i;
        int row = ci >> 3, seg = ci & 7;
        CP_ASYNC(Qb + row * A_ROWB + seg * 16, Qg + (size_t)row * HDd + seg * 8);
    }
    stageKV(0, 0);
    CP_WAIT(0);
    __syncthreads();

    uint32_t qf[4][4];
    #pragma unroll
    for (int k16 = 0; k16 < 4; k16++)
        ldsm_x4(qf[k16], ldsm_addr(Qb, i0, k16 * 32, A_ROWB, lane));

    float O[8][4];
    #pragma unroll
    for (int nf = 0; nf < 8; nf++)
        #pragma unroll
        for (int r = 0; r < 4; r++) O[nf][r] = 0.f;
    float rs0 = 0.f, rs1 = 0.f;

    for (int tt = 0; tt < 8; tt++) {
        const int buf = tt & 1;
        if (tt < 7) { stageKV((tt + 1) * 128, buf ^ 1); CP_WAIT(1); }
        else        { CP_WAIT(0); }
        __syncthreads();

        const uint32_t kb = Kb + buf * AKV_BYTES;
        const uint32_t vb = Vb + buf * AKV_BYTES;

        #pragma unroll
        for (int half = 0; half < 2; half++) {
            const int t0 = tt * 128 + half * 64;
            const int r0 = half * 64;    // row offset within 128-row buffer

            // S = Q K^T (log2 units; Q prescaled)
            float S[8][4];
            #pragma unroll
            for (int nf = 0; nf < 8; nf++)
                #pragma unroll
                for (int r = 0; r < 4; r++) S[nf][r] = 0.f;
            #pragma unroll
            for (int k16 = 0; k16 < 4; k16++) {
                #pragma unroll
                for (int nfp = 0; nfp < 4; nfp++) {
                    uint32_t r[4];
                    ldsm_x4(r, ldsm_addr(kb, r0 + nfp * 16, k16 * 32, A_ROWB, lane));
                    mma16(S[2*nfp],     qf[k16], r[0], r[2]);
                    mma16(S[2*nfp + 1], qf[k16], r[1], r[3]);
                }
            }

            // P = ex2(S) * mask (fp16 mask loads), packed fp16; rowsum fp32
            uint32_t Pp[8][2];
            #pragma unroll
            for (int nf = 0; nf < 8; nf++) {
                const __half* mp = mbase + (size_t)g * Ss + t0 + nf * 8 + 2 * tig;
                float2 m01 = __half22float2(*(const __half2*)mp);
                float2 m23 = __half22float2(*(const __half2*)(mp + 8 * Ss));
                float e0 = ex2f(S[nf][0]) * m01.x;
                float e1 = ex2f(S[nf][1]) * m01.y;
                float e2 = ex2f(S[nf][2]) * m23.x;
                float e3 = ex2f(S[nf][3]) * m23.y;
                rs0 += e0 + e1;
                rs1 += e2 + e3;
                Pp[nf][0] = h2u(__floats2half2_rn(e0, e1));
                Pp[nf][1] = h2u(__floats2half2_rn(e2, e3));
            }

            // O += P V
            #pragma unroll
            for (int kt = 0; kt < 4; kt++) {
                #pragma unroll
                for (int nfp = 0; nfp < 4; nfp++) {
                    uint32_t r[4];
                    ldsm_x4_t(r, ldsm_addr(vb, r0 + kt * 16, nfp * 32, A_ROWB, lane));
                    uint32_t a[4] = { Pp[2*kt][0], Pp[2*kt][1],
                                      Pp[2*kt + 1][0], Pp[2*kt + 1][1] };
                    mma16(O[2*nfp],     a, r[0], r[1]);
                    mma16(O[2*nfp + 1], a, r[2], r[3]);
                }
            }
        }
        __syncthreads();   // protect buffers before next iter's stage
    }

    // normalize + store
    rs0 += __shfl_xor_sync(0xffffffffu, rs0, 1);
    rs0 += __shfl_xor_sync(0xffffffffu, rs0, 2);
    rs1 += __shfl_xor_sync(0xffffffffu, rs1, 1);
    rs1 += __shfl_xor_sync(0xffffffffu, rs1, 2);
    const float inv0 = 1.0f / (rs0 + 1e-8f);
    const float inv1 = 1.0f / (rs1 + 1e-8f);
    float* o0 = out + ((size_t)b * Ss + q0 + i0 + g) * Dd + h * HDd;
    float* o1 = o0 + 8 * Dd;
    #pragma unroll
    for (int nf = 0; nf < 8; nf++) {
        int d = nf * 8 + 2 * tig;
        *(float2*)(o0 + d) = make_float2(O[nf][0] * inv0, O[nf][1] * inv0);
        *(float2*)(o1 + d) = make_float2(O[nf][2] * inv1, O[nf][3] * inv1);
    }
}

// ---------------------------------------------------------------------------
extern "C" void kernel_launch(void* const* d_in, const int* in_sizes, int n_in,
                              void* d_out, int out_size)
{
    const float* x    = (const float*)d_in[0];
    const float* mask = (const float*)d_in[1];
    const float* Wq   = (const float*)d_in[2];
    const float* Wk   = (const float*)d_in[3];
    const float* Wv   = (const float*)d_in[4];
    float* out = (float*)d_out;

    __half* gX; cudaGetSymbolAddress((void**)&gX, g_X16);
    __half* gM; cudaGetSymbolAddress((void**)&gM, g_M16);

    // 1) fp32 -> fp16 pre-pass (x, weights, mask)
    const int n4x = Mtot * Dd / 4;
    const int n4w = Dd * Dd / 4;
    const int n4m = Bb * Ss * Ss / 4;
    conv_fp16<<<(n4x + 255) / 256, 256>>>((const float4*)x, (__half2*)gX, n4x);
    {
        dim3 wgrid((n4w + 255) / 256, 1, 3);
        conv_w3<<<wgrid, 256>>>((const float4*)Wq, (const float4*)Wk,
                                (const float4*)Wv, n4w);
    }
    conv_fp16<<<(n4m + 255) / 256, 256>>>((const float4*)mask, (__half2*)gM, n4m);

    // 2) projections (fp16 HMMA, 3-stage pipeline, 1 barrier/K-step)
    cudaFuncSetAttribute(proj16_kernel, cudaFuncAttributeMaxDynamicSharedMemorySize,
                         PROJ_SMEM);
    dim3 pgrid(Dd / 128, Mtot / 128, 3);
    proj16_kernel<<<pgrid, 256, PROJ_SMEM>>>();

    // 3) attention (fp16 HMMA, occ 2, 128-row KV stages)
    cudaFuncSetAttribute(attn16_kernel, cudaFuncAttributeMaxDynamicSharedMemorySize,
                         ATTN_SMEM);
    dim3 agrid(Ss / 128, BHh);              // (8, 128)
    attn16_kernel<<<agrid, 256, ATTN_SMEM>>>(out);
}